// round 11
// baseline (speedup 1.0000x reference)
#include <cuda_runtime.h>
#include <cstdint>

// FastSeqProp: instance-norm(L=200) -> scale/shift -> softmax over C=4
// -> exact JAX threefry categorical (key 42, partitionable) -> straight-through
// -> pad to (N,4,600); outputs [softmax_padded, sampled_padded].
//
// R11: 2 sequences per CTA. Per-sequence float math and reduction order are
// bit-identical to the validated 1-flip kernel (rel_err 5.770226e-4); this
// round only doubles per-thread independent work (ILP) and halves barrier
// overhead per sequence. Warp 7 remains the DMA/pad warp.

#define LEN   200
#define LPAD  600
#define NCH   4
#define EPSV  1e-5f
#define TINYF 1.17549435e-38f

__device__ __forceinline__ uint32_t rotl32(uint32_t x, int r) {
    return (x << r) | (x >> (32 - r));
}

__device__ __forceinline__ void tf_round(uint32_t& x0, uint32_t& x1, int r) {
    x0 += x1;
    x1 = rotl32(x1, r);
    x1 ^= x0;
}

__device__ __forceinline__ uint32_t tf_bits_k42(uint32_t idx) {
    // threefry2x32, key=(0,42), counter=(0, idx); out = x0 ^ x1 (partitionable)
    const uint32_t ks0 = 0u;
    const uint32_t ks1 = 42u;
    const uint32_t ks2 = 0x1BD11BDAu ^ ks0 ^ ks1;
    uint32_t x0 = 0u + ks0;
    uint32_t x1 = idx + ks1;

    tf_round(x0, x1, 13); tf_round(x0, x1, 15); tf_round(x0, x1, 26); tf_round(x0, x1, 6);
    x0 += ks1; x1 += ks2 + 1u;
    tf_round(x0, x1, 17); tf_round(x0, x1, 29); tf_round(x0, x1, 16); tf_round(x0, x1, 24);
    x0 += ks2; x1 += ks0 + 2u;
    tf_round(x0, x1, 13); tf_round(x0, x1, 15); tf_round(x0, x1, 26); tf_round(x0, x1, 6);
    x0 += ks0; x1 += ks1 + 3u;
    tf_round(x0, x1, 17); tf_round(x0, x1, 29); tf_round(x0, x1, 16); tf_round(x0, x1, 24);
    x0 += ks1; x1 += ks2 + 4u;
    tf_round(x0, x1, 13); tf_round(x0, x1, 15); tf_round(x0, x1, 26); tf_round(x0, x1, 6);
    x0 += ks2; x1 += ks0 + 5u;

    return x0 ^ x1;
}

// w = -log(u), u = uniform in [tiny,1) from bits; exact logf (matches XLA).
__device__ __forceinline__ float expw_from_bits(uint32_t bits) {
    float f = __uint_as_float((bits >> 9) | 0x3f800000u) - 1.0f;
    float u = fmaxf(f, TINYF);
    return 0.0f - logf(u);
}

__device__ __forceinline__ void cp_async16(void* smem_dst, const void* gmem_src) {
    uint32_t s = (uint32_t)__cvta_generic_to_shared(smem_dst);
    asm volatile("cp.async.cg.shared.global [%0], [%1], 16;" :: "r"(s), "l"(gmem_src));
}

// sw slot for flat draw j in [0,1600): seq = j/800, within-seq (l*4+c) layout
__device__ __forceinline__ uint32_t sw_slot(uint32_t j) {
    const uint32_t seq = (j >= 800u) ? 1u : 0u;
    const uint32_t jj  = j - seq * 800u;
    return seq * 800u + (jj & 3u) * LEN + (jj >> 2);
}

__global__ __launch_bounds__(256, 5) void fastseqprop_kernel(
    const float* __restrict__ ts,    // (N,4,200)
    const float* __restrict__ scw,   // (N,4,1)
    const float* __restrict__ shw,   // (N,4,1)
    const float* __restrict__ up,    // (N,4,200)
    const float* __restrict__ dn,    // (N,4,200)
    float* __restrict__ out,         // (2,N,4,600) flattened
    uint32_t half_out)               // N*4*600
{
    const uint32_t n    = blockIdx.x;        // handles sequences 2n, 2n+1
    const uint32_t t    = threadIdx.x;
    const uint32_t lane = t & 31u;
    const uint32_t wid  = t >> 5;

    __shared__ float  red[7][8];
    __shared__ float  bcm[8];            // means, [seq*4+c]
    __shared__ float  bcr[8];            // rsqrt(var+eps)
    __shared__ float  sw[2 * NCH * LEN]; // w = -log(u), [seq*800 + c*200 + l]
    __shared__ float4 spad[800];         // per seq: [up(200) | dn(200)]

    const uint32_t base = n * 1600u;     // flat gumbel/ts base for the pair

    // ---- issue memory first: warp7 pad prefetch, warps 0-6 ts preload ----
    const bool act = (t < LEN);
    float xs[8];
    if (wid == 7u) {
        const float4* up4 = (const float4*)up + n * 400u;
        const float4* dn4 = (const float4*)dn + n * 400u;
        #pragma unroll
        for (uint32_t i = 0; i < 25u; i++) {
            const uint32_t idx = i * 32u + lane;
            const uint32_t seq = (idx >= 400u) ? 1u : 0u;
            const uint32_t r   = idx - seq * 400u;
            const float4* src = (r < 200u) ? (up4 + seq * 200u + r)
                                           : (dn4 + seq * 200u + (r - 200u));
            cp_async16(&spad[idx], src);
        }
        asm volatile("cp.async.commit_group;" ::: "memory");
    } else if (act) {
        #pragma unroll
        for (int k = 0; k < 8; k++)
            xs[k] = ts[base + (uint32_t)k * LEN + t];   // k = seq*4 + c
    }

    // ---- dense threefry: 1600 draws; 6 per thread, 64 extra on warp 7 ----
    #pragma unroll
    for (uint32_t k = 0; k < 6u; k++) {
        const uint32_t j = t + k * 256u;
        sw[sw_slot(j)] = expw_from_bits(tf_bits_k42(base + j));
    }

    // ================= warp 7: extra draws, then DMA =================
    if (wid == 7u) {
        const uint32_t j6 = 1536u + lane;
        const uint32_t j7 = 1568u + lane;
        sw[sw_slot(j6)] = expw_from_bits(tf_bits_k42(base + j6));
        sw[sw_slot(j7)] = expw_from_bits(tf_bits_k42(base + j7));
        // publish sw writes (warps 0-6 bar.sync 1 before the argmin phase)
        asm volatile("bar.arrive 1, 256;" ::: "memory");

        asm volatile("cp.async.wait_group 0;" ::: "memory");
        float4* o0 = (float4*)out + n * 1200u;   // 2 seq × 600 f4
        float4* o1 = o0 + (half_out >> 2);
        #pragma unroll 1
        for (uint32_t i = 0; i < 25u; i++) {
            const uint32_t idx = i * 32u + lane;
            const uint32_t seq = (idx >= 400u) ? 1u : 0u;
            const uint32_t r   = idx - seq * 400u;
            uint32_t off;
            if (r < 200u) {
                const uint32_t ch = r / 50u;
                off = seq * 600u + ch * 150u + (r - ch * 50u);
            } else {
                const uint32_t rr = r - 200u;
                const uint32_t ch = rr / 50u;
                off = seq * 600u + ch * 150u + 100u + (rr - ch * 50u);
            }
            const float4 v = spad[idx];
            o0[off] = v;
            o1[off] = v;
        }
        return;
    }

    // ================= warps 0-6: norm + softmax + sample (2 seqs) =========
    // ---- pass 1: sums -> means (per-channel tree identical to validated) ----
    {
        float v[8];
        #pragma unroll
        for (int k = 0; k < 8; k++) v[k] = act ? xs[k] : 0.f;
        #pragma unroll
        for (int o = 16; o > 0; o >>= 1) {
            #pragma unroll
            for (int k = 0; k < 8; k++) v[k] += __shfl_down_sync(0xffffffffu, v[k], o);
        }
        if (lane == 0) {
            #pragma unroll
            for (int k = 0; k < 8; k++) red[wid][k] = v[k];
        }
    }
    asm volatile("bar.sync 2, 224;" ::: "memory");
    if (t < 8u) {
        float s = red[0][t];
        #pragma unroll
        for (int w = 1; w < 7; w++) s += red[w][t];
        bcm[t] = s / 200.0f;
    }
    asm volatile("bar.sync 2, 224;" ::: "memory");

    float ds[8];
    #pragma unroll
    for (int k = 0; k < 8; k++) ds[k] = act ? (xs[k] - bcm[k]) : 0.f;

    // ---- pass 2: centered sum of squares -> rsqrt(var+eps) ----
    {
        float v[8];
        #pragma unroll
        for (int k = 0; k < 8; k++) v[k] = ds[k] * ds[k];
        #pragma unroll
        for (int o = 16; o > 0; o >>= 1) {
            #pragma unroll
            for (int k = 0; k < 8; k++) v[k] += __shfl_down_sync(0xffffffffu, v[k], o);
        }
        if (lane == 0) {
            #pragma unroll
            for (int k = 0; k < 8; k++) red[wid][k] = v[k];
        }
    }
    // pairs with warp 7's bar.arrive: orders red writes AND warp7's sw writes
    asm volatile("bar.sync 1, 256;" ::: "memory");
    if (t < 8u) {
        float s = red[0][t];
        #pragma unroll
        for (int w = 1; w < 7; w++) s += red[w][t];
        bcr[t] = rsqrtf(s / 200.0f + EPSV);
    }
    asm volatile("bar.sync 2, 224;" ::: "memory");

    // ---- element phase (t < 200): both sequences ----
    if (act) {
        float* out0 = out;
        float* out1 = out + half_out;
        #pragma unroll
        for (uint32_t s = 0; s < 2u; s++) {
            const uint32_t wb4 = (2u * n + s) * NCH;
            float sc[4];
            #pragma unroll
            for (int c = 0; c < 4; c++)
                sc[c] = (ds[s * 4 + c] * bcr[s * 4 + c]) * scw[wb4 + (uint32_t)c]
                        + shw[wb4 + (uint32_t)c];

            const float mx = fmaxf(fmaxf(sc[0], sc[1]), fmaxf(sc[2], sc[3]));
            float ex[4];
            #pragma unroll
            for (int c = 0; c < 4; c++) ex[c] = expf(sc[c] - mx);
            const float ssum = ((ex[0] + ex[1]) + ex[2]) + ex[3];
            float soft[4];
            #pragma unroll
            for (int c = 0; c < 4; c++) soft[c] = __fdividef(ex[c], ssum);

            // exponential-races argmin: argmin_c w_c / ex_c (cross-multiplied)
            const uint32_t swb = s * 800u;
            float wbv = sw[swb + t];
            float eb  = ex[0];
            int   bi  = 0;
            #pragma unroll
            for (int c = 1; c < 4; c++) {
                const float wc = sw[swb + (uint32_t)c * LEN + t];
                if (wc * eb < wbv * ex[c]) { wbv = wc; eb = ex[c]; bi = c; }
            }

            const uint32_t obase = (2u * n + s) * (NCH * LPAD);
            #pragma unroll
            for (int c = 0; c < 4; c++) {
                const float s_v = soft[c];
                const float oh  = (c == bi) ? 1.0f : 0.0f;
                const float samp = (oh - s_v) + s_v;   // straight-through
                const uint32_t mid = obase + (uint32_t)c * LPAD + LEN + t;
                out0[mid] = s_v;
                out1[mid] = samp;
            }
        }
    }
}

extern "C" void kernel_launch(void* const* d_in, const int* in_sizes, int n_in,
                              void* d_out, int out_size) {
    const float* ts  = (const float*)d_in[0];
    const float* scw = (const float*)d_in[1];
    const float* shw = (const float*)d_in[2];
    const float* up  = (const float*)d_in[3];
    const float* dn  = (const float*)d_in[4];
    float* out = (float*)d_out;

    const int nseq = in_sizes[0] / (NCH * LEN);          // 8192
    const uint32_t half_out = (uint32_t)(out_size / 2);  // N*4*600

    fastseqprop_kernel<<<nseq / 2, 256>>>(ts, scw, shw, up, dn, out, half_out);
}